// round 8
// baseline (speedup 1.0000x reference)
#include <cuda_runtime.h>
#include <cuda_bf16.h>

// Problem shape (fixed by the dataset)
constexpr int N  = 64;
constexpr int C  = 256;
constexpr int S  = 30;
constexpr int HW = 176;               // h*w = 16*11, contiguous innermost
constexpr int CSTRIDE = S * HW;       // 5280
constexpr int NSTRIDE = C * CSTRIDE;  // 1351680
constexpr int R  = 8;                 // conv radius: g[8] ~ 9e-10, below fp32 noise
constexpr int TOPK = 10;

// Scratch: stability scores, same layout as seqs [n, c, s, h*w]
__device__ float d_score[(long long)N * C * S * HW];
// Real-space low-pass kernel coefficients g[0..R]
__device__ float d_g[R + 1];

// ---------------------------------------------------------------------------
// Kernel 1: compute exact conv coefficients in double precision.
// g[d] = (1/256) * ( mask[0] + mask[128]*cos(pi*d) + 2*sum_{k=1..127} mask[k]*cos(2*pi*k*d/256) )
// mask[k] = exp(-0.5*(k/32)^2)   (freq_axis = k/128, sigma = 0.25 -> k/32)
// ---------------------------------------------------------------------------
__global__ void kinit() {
    const int d    = threadIdx.x >> 5;   // 0..R (one warp per coefficient)
    const int lane = threadIdx.x & 31;
    if (d > R) return;
    const double PI = 3.14159265358979323846;
    double part = 0.0;
    for (int k = 1 + lane; k <= 127; k += 32) {
        double fk = (double)k / 32.0;
        part += 2.0 * exp(-0.5 * fk * fk) * cos(PI * (double)k * (double)d / 128.0);
    }
    #pragma unroll
    for (int o = 16; o; o >>= 1)
        part += __shfl_down_sync(0xffffffffu, part, o);
    if (lane == 0) {
        double nyq = exp(-8.0) * ((d & 1) ? -1.0 : 1.0);   // mask[128]*cos(pi*d)
        d_g[d] = (float)((part + 1.0 + nyq) / 256.0);      // mask[0] = 1
    }
}

// ---------------------------------------------------------------------------
// Kernel 2: circular conv along c + stability score.
// Block = (hw-tile of 32, s, n). Smem tile [256][32], conflict-free
// (row stride = 32 banks -> lane maps to bank). 8 warps: warp w computes
// channels [32w, 32w+32) via a 48-value register window.
// ---------------------------------------------------------------------------
__global__ void __launch_bounds__(256) kconv(const float* __restrict__ seqs) {
    const int hw0 = blockIdx.x * 32;
    const int s   = blockIdx.y;
    const int n   = blockIdx.z;
    const int tw  = min(32, HW - hw0);   // 32 or 16 (last tile)

    __shared__ float X[256][32];

    const int lane = threadIdx.x & 31;
    const int wid  = threadIdx.x >> 5;
    const int base = n * NSTRIDE + s * HW + hw0;
    const bool act = lane < tw;

    // Load tile: each warp loads rows c ≡ wid (mod 8); lane = hw -> 128B coalesced
    #pragma unroll
    for (int i = 0; i < 32; ++i) {
        int c = (i << 3) + wid;
        X[c][lane] = act ? __ldg(&seqs[base + c * CSTRIDE + lane]) : 0.0f;
    }
    __syncthreads();

    float g[R + 1];
    #pragma unroll
    for (int d = 0; d <= R; ++d) g[d] = d_g[d];

    if (!act) return;

    const int c0 = wid << 5;
    float xv[32 + 2 * R];
    #pragma unroll
    for (int i = 0; i < 32 + 2 * R; ++i)
        xv[i] = X[(c0 - R + i) & 255][lane];

    #pragma unroll
    for (int j = 0; j < 32; ++j) {
        const float x  = xv[j + R];
        float acc = g[0] * x;
        #pragma unroll
        for (int d = 1; d <= R; ++d)
            acc = fmaf(g[d], xv[j + R - d] + xv[j + R + d], acc);
        const float denom = fabsf(acc - x) + 1e-6f;
        const float sc    = __fdividef(fabsf(acc), denom);
        d_score[base + (c0 + j) * CSTRIDE + lane] = sc;
    }
}

// ---------------------------------------------------------------------------
// Kernel 3: per-(n,c,hw) top-10 over s (stable tie-break = earliest s),
// mean of selected seqs, max-pool, sigmoid fusion.
// Block = one (n,c); thread = hw position; reads coalesced per s-row.
// ---------------------------------------------------------------------------
__global__ void __launch_bounds__(192) ktopk(const float* __restrict__ seqs,
                                             const float* __restrict__ fusion_logit,
                                             float* __restrict__ out) {
    const int t  = threadIdx.x;
    const int nc = blockIdx.x;
    if (t >= HW) return;
    const int base = nc * CSTRIDE + t;

    float v[S], sc[S];
    #pragma unroll
    for (int s = 0; s < S; ++s) {
        v[s]  = __ldg(&seqs[base + s * HW]);
        sc[s] = d_score[base + s * HW];
    }

    float maxv = v[0];
    #pragma unroll
    for (int s = 1; s < S; ++s) maxv = fmaxf(maxv, v[s]);

    // Top-10 scores via FMNMX insertion chain (scores are >= 0, so -1 is -inf)
    float top[TOPK];
    #pragma unroll
    for (int i = 0; i < TOPK; ++i) top[i] = -1.0f;
    #pragma unroll
    for (int s = 0; s < S; ++s) {
        float carry = sc[s];
        #pragma unroll
        for (int i = 0; i < TOPK; ++i) {
            float mx = fmaxf(top[i], carry);
            carry    = fminf(top[i], carry);
            top[i]   = mx;
        }
    }
    const float thr = top[TOPK - 1];

    // Accumulate: strictly greater first (at most 9), then earliest ties.
    // This reproduces jax.lax.top_k's stable (lowest-index-first) selection set.
    float sum = 0.0f;
    int taken = 0;
    #pragma unroll
    for (int s = 0; s < S; ++s)
        if (sc[s] > thr) { sum += v[s]; ++taken; }
    #pragma unroll
    for (int s = 0; s < S; ++s)
        if (sc[s] == thr && taken < TOPK) { sum += v[s]; ++taken; }

    const float lg    = fusion_logit[0];
    const float alpha = 1.0f / (1.0f + expf(-lg));
    out[nc * HW + t] = alpha * (sum * (1.0f / TOPK)) + (1.0f - alpha) * maxv;
}

// ---------------------------------------------------------------------------
extern "C" void kernel_launch(void* const* d_in, const int* in_sizes, int n_in,
                              void* d_out, int out_size) {
    const float* seqs  = (const float*)d_in[0];
    const float* logit = (const float*)d_in[1];
    float* out = (float*)d_out;

    kinit<<<1, (R + 1) * 32>>>();
    kconv<<<dim3((HW + 31) / 32, S, N), 256>>>(seqs);
    ktopk<<<N * C, 192>>>(seqs, logit, out);
}

// round 9
// speedup vs baseline: 1.0413x; 1.0413x over previous
#include <cuda_runtime.h>
#include <cstdint>

constexpr int N = 64, C = 256, S = 30, HW = 176;
constexpr int CSTR = S * HW, NSTR = C * CSTR;
constexpr int R = 8, TOPK = 10;
constexpr int H = 8;                      // hw per block
constexpr int CI = 128, NIT = 2;          // channels per iteration
constexpr int SLOTS = CI + 2 * R;         // 144 (with circular halo)
constexpr int P = 12;                     // smem pitch words: conflict-free
constexpr int SCH = 10, NCH = 3;          // s-chunks for load/compute overlap
constexpr int SMEMB = S * SLOTS * P * 4;  // 207360 B

__device__ float d_g[R + 1];

// g[d] = (1/256)(1 + 2*sum_{k=1..127} e^{-k^2/2048} cos(pi k d/128) + e^{-8} cos(pi d))
__global__ void kinit() {
    const int d = blockIdx.x, t = threadIdx.x;
    const double PI = 3.14159265358979323846;
    double k = (double)(t + 1);
    double term = exp(-k * k / 2048.0) * cos(PI * k * (double)d / 128.0);
    if (t != 127) term *= 2.0;            // Nyquist (k=128) counted once
    __shared__ double red[4];
    #pragma unroll
    for (int o = 16; o; o >>= 1) term += __shfl_down_sync(0xffffffffu, term, o);
    if ((t & 31) == 0) red[t >> 5] = term;
    __syncthreads();
    if (t == 0) d_g[d] = (float)((1.0 + red[0] + red[1] + red[2] + red[3]) / 256.0);
}

__global__ void __launch_bounds__(512)
kfused(const float* __restrict__ seqs, const float* __restrict__ flogit,
       float* __restrict__ out) {
    extern __shared__ float sm[];
    const int hw0 = blockIdx.x * H;
    const int n   = blockIdx.y;
    const int tid = threadIdx.x;
    const int hw  = tid & 7;
    const int cg  = tid >> 3;             // 0..63 -> channels 2cg, 2cg+1
    const int w0  = 2 * cg;               // window base slot
    const float alpha = 1.0f / (1.0f + expf(-flogit[0]));

    float g[R + 1];
    #pragma unroll
    for (int d = 0; d <= R; ++d) g[d] = d_g[d];

    #pragma unroll 1
    for (int it = 0; it < NIT; ++it) {
        const int cb = it * CI + C - R;   // slot -> channel (cb+slot)&255

        // Issue all 3 s-chunk load groups (rows of 32B, two 16B cp.asyncs each)
        #pragma unroll
        for (int ck = 0; ck < NCH; ++ck) {
            for (int i = tid; i < SLOTS * SCH * 2; i += 512) {
                int q = i & 1, r = i >> 1;
                int sl = r / SLOTS, slot = r - sl * SLOTS;
                int s = ck * SCH + sl;
                int c = (cb + slot) & 255;
                const float* src = seqs + (size_t)n * NSTR + (size_t)c * CSTR
                                   + s * HW + hw0 + q * 4;
                uint32_t dst = (uint32_t)__cvta_generic_to_shared(
                    sm + (s * SLOTS + slot) * P + q * 4);
                asm volatile("cp.async.cg.shared.global [%0],[%1],16;"
                             :: "r"(dst), "l"(src));
            }
            asm volatile("cp.async.commit_group;" ::: "memory");
        }

        float sc[2][S], top[2][TOPK];
        #pragma unroll
        for (int ch = 0; ch < 2; ++ch)
            #pragma unroll
            for (int i = 0; i < TOPK; ++i) top[ch][i] = -1.0f;

        // Compute chunk k while chunk k+1 streams in
        #pragma unroll
        for (int ck = 0; ck < NCH; ++ck) {
            if (ck == 0)      asm volatile("cp.async.wait_group 2;" ::: "memory");
            else if (ck == 1) asm volatile("cp.async.wait_group 1;" ::: "memory");
            else              asm volatile("cp.async.wait_group 0;" ::: "memory");
            __syncthreads();

            #pragma unroll
            for (int j = 0; j < SCH; ++j) {
                const int s = ck * SCH + j;
                const float* b = sm + (s * SLOTS + w0) * P + hw;
                float w[2 * R + 2];
                #pragma unroll
                for (int u = 0; u < 2 * R + 2; ++u) w[u] = b[u * P];
                #pragma unroll
                for (int ch = 0; ch < 2; ++ch) {
                    const float x = w[ch + R];
                    float acc = g[0] * x;
                    #pragma unroll
                    for (int d = 1; d <= R; ++d)
                        acc = fmaf(g[d], w[ch + R - d] + w[ch + R + d], acc);
                    const float sv = __fdividef(fabsf(acc), fabsf(acc - x) + 1e-6f);
                    sc[ch][s] = sv;
                    float cr = sv;             // triangular insertion chain
                    #pragma unroll
                    for (int i = 0; i < TOPK; ++i) {
                        if (i <= s) {
                            float m = fmaxf(top[ch][i], cr);
                            cr      = fminf(top[ch][i], cr);
                            top[ch][i] = m;
                        }
                    }
                }
            }
        }

        // Threshold + stable-tie selection + max pool + fused output
        #pragma unroll
        for (int ch = 0; ch < 2; ++ch) {
            const float thr = top[ch][TOPK - 1];
            int bud = TOPK;
            #pragma unroll
            for (int s = 0; s < S; ++s) bud -= (sc[ch][s] > thr);
            const int slot = w0 + ch + R;
            float sum = 0.0f, mx = -3.0e38f;
            #pragma unroll
            for (int s = 0; s < S; ++s) {
                const float v = sm[(s * SLOTS + slot) * P + hw];
                mx = fmaxf(mx, v);
                bool tk = sc[ch][s] > thr;
                if (sc[ch][s] == thr && bud > 0) { tk = true; --bud; }
                if (tk) sum += v;
            }
            const int c = it * CI + 2 * cg + ch;
            out[(n * C + c) * HW + hw0 + hw] =
                alpha * (sum * (1.0f / TOPK)) + (1.0f - alpha) * mx;
        }
        __syncthreads();   // tile reads done before next iteration overwrites
    }
}

extern "C" void kernel_launch(void* const* d_in, const int* in_sizes, int n_in,
                              void* d_out, int out_size) {
    const float* seqs  = (const float*)d_in[0];
    const float* logit = (const float*)d_in[1];
    float* out = (float*)d_out;
    cudaFuncSetAttribute(kfused, cudaFuncAttributeMaxDynamicSharedMemorySize, SMEMB);
    kinit<<<R + 1, 128>>>();
    kfused<<<dim3(HW / H, N), 512, SMEMB>>>(seqs, logit, out);
}